// round 14
// baseline (speedup 1.0000x reference)
#include <cuda_runtime.h>
#include <cuda_fp16.h>
#include <cstdint>

// ---------------- problem constants ----------------
#define HID 512
#define MID 256
#define COND_D 256
#define OP_D 32
#define EX_D 32
#define LL 16
#define NN 1024
#define TT 8
#define BB (LL*NN)          // 16384
#define G4 (4*HID)          // 2048
#define IN2 (OP_D+EX_D+MID) // 320
#define TREE_CTAS 128

// ---------------- scratch (device globals; no allocation allowed) ----------------
__device__ __align__(16) __half g_h1[2][BB*HID];
__device__ float g_c1[BB*HID];
__device__ float g_last[BB*MID];
__device__ __align__(16) __half g_cat[BB*IN2];
__device__ float g_xp2[(long)BB*G4];               // gate-interleaved
__device__ float g_ph[(NN+1)*HID];
__device__ float g_pc[(NN+1)*HID];
__device__ __align__(16) __half g_hin[NN*HID];
__device__ float g_cin[NN*HID];
__device__ float g_bs1[G4];                        // gate-interleaved bias
__device__ float g_bs2[G4];
__device__ float g_mu[HID];
__device__ float g_rstd[HID];
__device__ int   g_map32[LL*NN*2];
__device__ int   g_map_is64;
__device__ unsigned int g_bar_gen;
__device__ unsigned int g_bar_cnt;
// fp16 weights (LSTM weights gate-interleaved)
__device__ __align__(16) __half g_w1ih[G4*COND_D];
__device__ __align__(16) __half g_w1hh[G4*HID];
__device__ __align__(16) __half g_condw[MID*HID];
__device__ __align__(16) __half g_w2ih[G4*IN2];
__device__ __align__(16) __half g_w2hh[G4*HID];
__device__ __align__(16) __half g_cond16[(long)BB*TT*COND_D];

// ---------------- low-level helpers ----------------
__device__ __forceinline__ uint32_t smem_u32(const void* p) {
    uint32_t a;
    asm("{ .reg .u64 t; cvta.to.shared.u64 t, %1; cvt.u32.u64 %0, t; }" : "=r"(a) : "l"(p));
    return a;
}
__device__ __forceinline__ void ldmx4(uint32_t* r, uint32_t addr) {
    asm volatile("ldmatrix.sync.aligned.m8n8.x4.shared.b16 {%0,%1,%2,%3}, [%4];"
        : "=r"(r[0]), "=r"(r[1]), "=r"(r[2]), "=r"(r[3]) : "r"(addr));
}
__device__ __forceinline__ void mma16816(float* d, const uint32_t* a, const uint32_t* b) {
    asm volatile("mma.sync.aligned.m16n8k16.row.col.f32.f16.f16.f32 "
        "{%0,%1,%2,%3}, {%4,%5,%6,%7}, {%8,%9}, {%0,%1,%2,%3};"
        : "+f"(d[0]), "+f"(d[1]), "+f"(d[2]), "+f"(d[3])
        : "r"(a[0]), "r"(a[1]), "r"(a[2]), "r"(a[3]), "r"(b[0]), "r"(b[1]));
}
#define CPASYNC16(dst, src) asm volatile("cp.async.cg.shared.global [%0], [%1], 16;" :: "r"(dst), "l"(src))
#define CP_COMMIT() asm volatile("cp.async.commit_group;" ::: "memory")
#define CP_WAIT1()  asm volatile("cp.async.wait_group 1;" ::: "memory")
#define CP_WAIT0()  asm volatile("cp.async.wait_group 0;" ::: "memory")

__device__ __forceinline__ float sigf(float x) { return 1.f / (1.f + expf(-x)); }

// inter-CTA generation barrier (all TREE_CTAS CTAs resident)
__device__ __forceinline__ void grid_sync() {
    __syncthreads();
    if (threadIdx.x == 0) {
        __threadfence();
        unsigned int gen = atomicAdd(&g_bar_gen, 0u);
        if (atomicAdd(&g_bar_cnt, 1u) == TREE_CTAS - 1u) {
            atomicExch(&g_bar_cnt, 0u);
            atomicAdd(&g_bar_gen, 1u);
        } else {
            while (atomicAdd(&g_bar_gen, 0u) == gen) { __nanosleep(64); }
        }
    }
    __syncthreads();
}

#define FLAG_RELU  2
#define FLAG_CELL1 4
#define FLAG_CZERO 16

// ---------------- GEMM tile config ----------------
#define TSZ   16384
#define OFF_A 0
#define OFF_B TSZ
#define BUFSZ  (2*TSZ)          // 32 KB per stage
#define STG_LD 132
#define STG_BYTES (128*STG_LD*4)   // 67584
#define SMEM_TOTAL STG_BYTES

// ---------------- mma.sync fp16 GEMM + optional fused CELL1 epilogue ----------
__global__ __launch_bounds__(256, 2) void gemm_mma(
    const __half* __restrict__ A1, int lda1, int K1, const __half* __restrict__ B1,
    const __half* __restrict__ A2, int lda2, int K2, const __half* __restrict__ B2,
    const float* __restrict__ bias,
    float* __restrict__ C, int M, int N, int flags,
    float* __restrict__ cellc, __half* __restrict__ hout)
{
    extern __shared__ char smem[];
    uint32_t sb = smem_u32(smem);

    int tid = threadIdx.x;
    int wid = tid >> 5, lane = tid & 31;
    int m0 = blockIdx.y * 128, n0 = blockIdx.x * 128;
    int wm = wid & 1, wn = wid >> 1;

    float acc[4][4][4];
    #pragma unroll
    for (int i = 0; i < 4; i++)
        #pragma unroll
        for (int j = 0; j < 4; j++)
            #pragma unroll
            for (int k = 0; k < 4; k++) acc[i][j][k] = 0.f;

    int nc1 = K1 / 64, nc2 = K2 / 64, ncT = nc1 + nc2;
    int r = tid >> 1;
    int half = tid & 1;

    auto issue = [&](int ci, int buf) {
        int ph2 = (ci >= nc1);
        const __half* Ap = ph2 ? A2 : A1;
        const __half* Bp = ph2 ? B2 : B1;
        int lda = ph2 ? lda2 : lda1;
        int ldb = ph2 ? K2 : K1;
        int k0 = (ci - (ph2 ? nc1 : 0)) * 64 + half * 32;
        const __half* pA = Ap + (size_t)(m0 + r) * lda + k0;
        const __half* pB = Bp + (size_t)(n0 + r) * ldb + k0;
        uint32_t base = sb + buf * BUFSZ;
        #pragma unroll
        for (int g = 0; g < 4; g++) {
            uint32_t doff = (uint32_t)(r * 128 + (((half * 4 + g) ^ (r & 7)) * 16));
            CPASYNC16(base + OFF_A + doff, pA + g * 8);
            CPASYNC16(base + OFF_B + doff, pB + g * 8);
        }
    };

    issue(0, 0);
    CP_COMMIT();

    for (int ci = 0; ci < ncT; ci++) {
        if (ci + 1 < ncT) {
            issue(ci + 1, (ci + 1) & 1);
            CP_COMMIT();
            CP_WAIT1();
        } else {
            CP_WAIT0();
        }
        __syncthreads();

        uint32_t base = sb + (ci & 1) * BUFSZ;
        #pragma unroll
        for (int s = 0; s < 4; s++) {
            uint32_t af[4][4];
            #pragma unroll
            for (int mt = 0; mt < 4; mt++) {
                int rr = wm * 64 + mt * 16 + (lane & 15);
                int g = (s * 2 + (lane >> 4)) ^ (rr & 7);
                ldmx4(af[mt], base + OFF_A + (uint32_t)(rr * 128 + g * 16));
            }
            uint32_t bf[4][2];
            #pragma unroll
            for (int ntp = 0; ntp < 2; ntp++) {
                int rr = wn * 32 + ntp * 16 + (lane & 15);
                int g = (s * 2 + (lane >> 4)) ^ (rr & 7);
                uint32_t t[4];
                ldmx4(t, base + OFF_B + (uint32_t)(rr * 128 + g * 16));
                bf[2*ntp][0] = t[0]; bf[2*ntp][1] = t[2];
                bf[2*ntp+1][0] = t[1]; bf[2*ntp+1][1] = t[3];
            }
            #pragma unroll
            for (int mt = 0; mt < 4; mt++)
                #pragma unroll
                for (int nt = 0; nt < 4; nt++)
                    mma16816(acc[mt][nt], af[mt], bf[nt]);
        }
        __syncthreads();
    }

    if (flags & FLAG_CELL1) {
        float* stg = (float*)smem;
        #pragma unroll
        for (int mt = 0; mt < 4; mt++) {
            int rowl = wm * 64 + mt * 16 + (lane >> 2);
            #pragma unroll
            for (int nt = 0; nt < 4; nt++) {
                int coll = wn * 32 + nt * 8 + (lane & 3) * 2;
                float* d = acc[mt][nt];
                *(float2*)&stg[rowl * STG_LD + coll]       = make_float2(d[0], d[1]);
                *(float2*)&stg[(rowl + 8) * STG_LD + coll] = make_float2(d[2], d[3]);
            }
        }
        __syncthreads();
        #pragma unroll
        for (int it = 0; it < 16; it++) {
            int idx = it * 256 + tid;
            int q = idx & 31, rowl = idx >> 5;
            int rowg = m0 + rowl;
            int j = (n0 >> 2) + q;
            float4 v = *(float4*)&stg[rowl * STG_LD + 4 * q];
            float4 b = *(const float4*)(bias + n0 + 4 * q);
            v.x += b.x; v.y += b.y; v.z += b.z; v.w += b.w;
            float ii = sigf(v.x), ff = sigf(v.y), gg = tanhf(v.z), oo = sigf(v.w);
            long ci = (long)rowg * HID + j;
            float cprev = (flags & FLAG_CZERO) ? 0.f : cellc[ci];
            float cn = ff * cprev + ii * gg;
            cellc[ci] = cn;
            hout[ci] = __float2half(oo * tanhf(cn));
        }
    } else {
        #pragma unroll
        for (int mt = 0; mt < 4; mt++) {
            int row0 = m0 + wm * 64 + mt * 16 + (lane >> 2);
            #pragma unroll
            for (int nt = 0; nt < 4; nt++) {
                int col = n0 + wn * 32 + nt * 8 + (lane & 3) * 2;
                float* d = acc[mt][nt];
                float b0 = 0.f, b1 = 0.f;
                if (bias) { b0 = __ldg(bias + col); b1 = __ldg(bias + col + 1); }
                float v0 = d[0] + b0, v1 = d[1] + b1;
                float v2 = d[2] + b0, v3 = d[3] + b1;
                if (flags & FLAG_RELU) {
                    v0 = fmaxf(v0, 0.f); v1 = fmaxf(v1, 0.f);
                    v2 = fmaxf(v2, 0.f); v3 = fmaxf(v3, 0.f);
                }
                float* C0 = C + (size_t)row0 * N + col;
                float* C1 = C + (size_t)(row0 + 8) * N + col;
                C0[0] = v0; C0[1] = v1;
                C1[0] = v2; C1[1] = v3;
            }
        }
    }
}

// ---------------- persistent tree kernel ----------
__global__ __launch_bounds__(256, 1) void tree_persistent(
    const __half* __restrict__ w2hh, const float* __restrict__ xp2,
    const int* __restrict__ map32,
    __half* __restrict__ hin, float* __restrict__ cin,
    float* __restrict__ ph, float* __restrict__ pc)
{
    extern __shared__ char smem[];
    uint32_t sb = smem_u32(smem);
    int tid = threadIdx.x;
    int cb = blockIdx.x;
    int wid = tid >> 5, lane = tid & 31;
    int m0 = (cb >> 4) * 128;
    int n0 = (cb & 15) * 128;
    int wm = wid & 1, wn = wid >> 1;
    int r = tid >> 1;
    int half = tid & 1;

    {
        const float* g0 = xp2 + (long)(LL - 1) * NN * G4;
        #pragma unroll 4
        for (int it = 0; it < 16; it++) {
            int idx = cb * 4096 + it * 256 + tid;
            int b = idx >> 9, j = idx & 511;
            float4 v = *(const float4*)(g0 + (long)b * G4 + 4 * j);
            float ii = sigf(v.x), gg = tanhf(v.z), oo = sigf(v.w);
            float cn = ii * gg;
            pc[(b + 1) * HID + j] = cn;
            ph[(b + 1) * HID + j] = oo * tanhf(cn);
        }
    }
    grid_sync();

    for (int lvl = LL - 2; lvl >= 0; lvl--) {
        const int* mp = map32 + lvl * NN * 2;
        #pragma unroll 4
        for (int it = 0; it < 16; it++) {
            int idx = cb * 4096 + it * 256 + tid;
            int n = idx >> 9, j = idx & 511;
            int a = mp[n * 2], b2 = mp[n * 2 + 1];
            a = min(max(a, 0), NN); b2 = min(max(b2, 0), NN);
            hin[idx] = __float2half(0.5f * (ph[a * HID + j] + ph[b2 * HID + j]));
            cin[idx] = 0.5f * (pc[a * HID + j] + pc[b2 * HID + j]);
        }
        grid_sync();

        float acc[4][4][4];
        #pragma unroll
        for (int i = 0; i < 4; i++)
            #pragma unroll
            for (int j = 0; j < 4; j++)
                #pragma unroll
                for (int k = 0; k < 4; k++) acc[i][j][k] = 0.f;

        auto issue = [&](int ci, int buf) {
            int k0 = ci * 64 + half * 32;
            const __half* pA = hin + (size_t)(m0 + r) * HID + k0;
            const __half* pB = w2hh + (size_t)(n0 + r) * HID + k0;
            uint32_t base = sb + buf * BUFSZ;
            #pragma unroll
            for (int g = 0; g < 4; g++) {
                uint32_t doff = (uint32_t)(r * 128 + (((half * 4 + g) ^ (r & 7)) * 16));
                CPASYNC16(base + OFF_A + doff, pA + g * 8);
                CPASYNC16(base + OFF_B + doff, pB + g * 8);
            }
        };

        issue(0, 0);
        CP_COMMIT();
        for (int ci = 0; ci < 8; ci++) {
            if (ci + 1 < 8) {
                issue(ci + 1, (ci + 1) & 1);
                CP_COMMIT();
                CP_WAIT1();
            } else {
                CP_WAIT0();
            }
            __syncthreads();
            uint32_t base = sb + (ci & 1) * BUFSZ;
            #pragma unroll
            for (int s = 0; s < 4; s++) {
                uint32_t af[4][4];
                #pragma unroll
                for (int mt = 0; mt < 4; mt++) {
                    int rr = wm * 64 + mt * 16 + (lane & 15);
                    int g = (s * 2 + (lane >> 4)) ^ (rr & 7);
                    ldmx4(af[mt], base + OFF_A + (uint32_t)(rr * 128 + g * 16));
                }
                uint32_t bf[4][2];
                #pragma unroll
                for (int ntp = 0; ntp < 2; ntp++) {
                    int rr = wn * 32 + ntp * 16 + (lane & 15);
                    int g = (s * 2 + (lane >> 4)) ^ (rr & 7);
                    uint32_t t[4];
                    ldmx4(t, base + OFF_B + (uint32_t)(rr * 128 + g * 16));
                    bf[2*ntp][0] = t[0]; bf[2*ntp][1] = t[2];
                    bf[2*ntp+1][0] = t[1]; bf[2*ntp+1][1] = t[3];
                }
                #pragma unroll
                for (int mt = 0; mt < 4; mt++)
                    #pragma unroll
                    for (int nt = 0; nt < 4; nt++)
                        mma16816(acc[mt][nt], af[mt], bf[nt]);
            }
            __syncthreads();
        }

        float* stg = (float*)smem;
        #pragma unroll
        for (int mt = 0; mt < 4; mt++) {
            int rowl = wm * 64 + mt * 16 + (lane >> 2);
            #pragma unroll
            for (int nt = 0; nt < 4; nt++) {
                int coll = wn * 32 + nt * 8 + (lane & 3) * 2;
                float* d = acc[mt][nt];
                *(float2*)&stg[rowl * STG_LD + coll]       = make_float2(d[0], d[1]);
                *(float2*)&stg[(rowl + 8) * STG_LD + coll] = make_float2(d[2], d[3]);
            }
        }
        __syncthreads();
        const float* ad = xp2 + (long)lvl * NN * G4;
        #pragma unroll
        for (int it = 0; it < 16; it++) {
            int idx = it * 256 + tid;
            int q = idx & 31, rowl = idx >> 5;
            int rowg = m0 + rowl;
            int j = (n0 >> 2) + q;
            float4 v = *(float4*)&stg[rowl * STG_LD + 4 * q];
            float4 a = *(const float4*)(ad + (size_t)rowg * G4 + n0 + 4 * q);
            v.x += a.x; v.y += a.y; v.z += a.z; v.w += a.w;
            float ii = sigf(v.x), ff = sigf(v.y), gg = tanhf(v.z), oo = sigf(v.w);
            float cn = ff * cin[(long)rowg * HID + j] + ii * gg;
            long po = (long)(rowg + 1) * HID + j;
            pc[po] = cn;
            ph[po] = oo * tanhf(cn);
        }
        grid_sync();
    }
}

// ---------------- conversion kernels (vectorized) ----------------
__global__ void cvt_arr4(const float4* __restrict__ x, __half2* __restrict__ o, long n4) {
    long i = (long)blockIdx.x * blockDim.x + threadIdx.x;
    if (i >= n4) return;
    float4 v = x[i];
    o[i*2]   = __floats2half2_rn(v.x, v.y);
    o[i*2+1] = __floats2half2_rn(v.z, v.w);
}
__global__ void cvt_perm_w(const float* __restrict__ x, __half* __restrict__ o,
                           int K, long n) {
    long idx = (long)blockIdx.x * blockDim.x + threadIdx.x;
    if (idx >= n) return;
    int col = (int)(idx % K);
    long row = idx / K;
    int g = (int)(row >> 9), j = (int)(row & 511);
    o[((long)(4 * j + g)) * K + col] = __float2half(x[idx]);
}
__global__ void bias_perm(const float* __restrict__ bih, const float* __restrict__ bhh,
                          float* __restrict__ o) {
    int i = blockIdx.x * blockDim.x + threadIdx.x;
    if (i >= G4) return;
    int g = i >> 9, j = i & 511;
    o[4 * j + g] = bih[i] + bhh[i];
}

// ---------------- mapping dtype normalization (parallel detect) ----------------
__global__ void detect_map(const long long* __restrict__ raw) {
    __shared__ int bad;
    if (threadIdx.x == 0) bad = 0;
    __syncthreads();
    long long v = raw[threadIdx.x];
    if (v < 0 || v > NN) atomicOr(&bad, 1);
    __syncthreads();
    if (threadIdx.x == 0) g_map_is64 = bad ? 0 : 1;
}
__global__ void convert_map(const void* __restrict__ raw, int* __restrict__ o) {
    int i = blockIdx.x * blockDim.x + threadIdx.x;
    if (i >= LL*NN*2) return;
    if (g_map_is64) o[i] = (int)((const long long*)raw)[i];
    else            o[i] = ((const int*)raw)[i];
}

// ---------------- elementwise kernels ----------------
__global__ void concat_in2(const float* __restrict__ ops, const float* __restrict__ ex,
                           const float* __restrict__ last,
                           const float* __restrict__ mu, const float* __restrict__ rstd,
                           const float* __restrict__ gam, const float* __restrict__ bet,
                           __half* __restrict__ cat) {
    long idx = (long)blockIdx.x * blockDim.x + threadIdx.x;
    if (idx >= (long)BB * IN2) return;
    int r = (int)(idx / IN2), k = (int)(idx % IN2);
    float v;
    if (k < OP_D)            v = ops[(long)r * OP_D + k];
    else if (k < OP_D+EX_D)  v = ex[(long)r * EX_D + (k - OP_D)];
    else {
        int c = k - OP_D - EX_D;
        float x = last[(long)r * MID + c];
        v = gam[c] * (x - mu[c]) * rstd[c] + bet[c];
    }
    cat[idx] = __float2half(v);
}

__global__ void bn_stats(const float* __restrict__ X, int Brows, int C,
                         float* __restrict__ mu, float* __restrict__ rstd) {
    int c = blockIdx.x * 32 + threadIdx.x;
    float s = 0.f, s2 = 0.f;
    for (int r = threadIdx.y; r < Brows; r += 8) {
        float v = X[(long)r * C + c];
        s += v; s2 += v * v;
    }
    __shared__ float sh[8][33], sh2[8][33];
    sh[threadIdx.y][threadIdx.x] = s;
    sh2[threadIdx.y][threadIdx.x] = s2;
    __syncthreads();
    if (threadIdx.y == 0) {
        #pragma unroll
        for (int y = 1; y < 8; y++) { s += sh[y][threadIdx.x]; s2 += sh2[y][threadIdx.x]; }
        float m = s / (float)Brows;
        float var = s2 / (float)Brows - m * m;
        mu[c] = m;
        rstd[c] = rsqrtf(var + 1e-5f);
    }
}

// phase-5: fused BN stats+apply over [NN, HID] -> out
__global__ void bn2_fused(const float* __restrict__ X,
                          const float* __restrict__ gam, const float* __restrict__ bet,
                          float* __restrict__ Y) {
    int c = blockIdx.x * 32 + threadIdx.x;
    float s = 0.f, s2 = 0.f;
    for (int r = threadIdx.y; r < NN; r += 8) {
        float v = X[(long)r * HID + c];
        s += v; s2 += v * v;
    }
    __shared__ float sh[8][33], sh2[8][33], smu[32], srs[32];
    sh[threadIdx.y][threadIdx.x] = s;
    sh2[threadIdx.y][threadIdx.x] = s2;
    __syncthreads();
    if (threadIdx.y == 0) {
        #pragma unroll
        for (int y = 1; y < 8; y++) { s += sh[y][threadIdx.x]; s2 += sh2[y][threadIdx.x]; }
        float m = s / (float)NN;
        float var = s2 / (float)NN - m * m;
        smu[threadIdx.x] = m;
        srs[threadIdx.x] = rsqrtf(var + 1e-5f);
    }
    __syncthreads();
    float m = smu[threadIdx.x], rs = srs[threadIdx.x];
    float gmv = gam[c], btv = bet[c];
    for (int r = threadIdx.y; r < NN; r += 8) {
        float v = X[(long)r * HID + c];
        Y[(long)r * HID + c] = gmv * (v - m) * rs + btv;
    }
}

// ---------------- launch ----------------
extern "C" void kernel_launch(void* const* d_in, const int* in_sizes, int n_in,
                              void* d_out, int out_size) {
    const float* ops   = (const float*)d_in[0];
    const float* extra = (const float*)d_in[1];
    const float* cond  = (const float*)d_in[2];
    const void*  mapping_raw = d_in[4];
    const float* W1ih = (const float*)d_in[5];
    const float* W1hh = (const float*)d_in[6];
    const float* b1ih = (const float*)d_in[7];
    const float* b1hh = (const float*)d_in[8];
    const float* condW = (const float*)d_in[9];
    const float* condb = (const float*)d_in[10];
    const float* bn1g = (const float*)d_in[11];
    const float* bn1b = (const float*)d_in[12];
    const float* W2ih = (const float*)d_in[13];
    const float* W2hh = (const float*)d_in[14];
    const float* b2ih = (const float*)d_in[15];
    const float* b2hh = (const float*)d_in[16];
    const float* bn2g = (const float*)d_in[17];
    const float* bn2b = (const float*)d_in[18];
    float* out = (float*)d_out;

    float *c1,*last,*xp2,*ph,*pc,*cin,*bs1,*bs2,*mu,*rstd;
    __half *h1a,*h1b,*cat,*hin,*w1ih,*w1hh,*condw,*w2ih,*w2hh,*cond16;
    int *map32;
    cudaGetSymbolAddress((void**)&h1a,  g_h1); h1b = h1a + (size_t)BB*HID;
    cudaGetSymbolAddress((void**)&c1,   g_c1);
    cudaGetSymbolAddress((void**)&last, g_last);
    cudaGetSymbolAddress((void**)&cat,  g_cat);
    cudaGetSymbolAddress((void**)&xp2,  g_xp2);
    cudaGetSymbolAddress((void**)&ph,   g_ph);
    cudaGetSymbolAddress((void**)&pc,   g_pc);
    cudaGetSymbolAddress((void**)&hin,  g_hin);
    cudaGetSymbolAddress((void**)&cin,  g_cin);
    cudaGetSymbolAddress((void**)&bs1,  g_bs1);
    cudaGetSymbolAddress((void**)&bs2,  g_bs2);
    cudaGetSymbolAddress((void**)&mu,   g_mu);
    cudaGetSymbolAddress((void**)&rstd, g_rstd);
    cudaGetSymbolAddress((void**)&map32, g_map32);
    cudaGetSymbolAddress((void**)&w1ih, g_w1ih);
    cudaGetSymbolAddress((void**)&w1hh, g_w1hh);
    cudaGetSymbolAddress((void**)&condw, g_condw);
    cudaGetSymbolAddress((void**)&w2ih, g_w2ih);
    cudaGetSymbolAddress((void**)&w2hh, g_w2hh);
    cudaGetSymbolAddress((void**)&cond16, g_cond16);

    cudaFuncSetAttribute(gemm_mma, cudaFuncAttributeMaxDynamicSharedMemorySize, SMEM_TOTAL);
    cudaFuncSetAttribute(tree_persistent, cudaFuncAttributeMaxDynamicSharedMemorySize, SMEM_TOTAL);

    // init (no c1 memset: step 0 uses FLAG_CZERO)
    cudaMemsetAsync(ph, 0, (size_t)(NN+1)*HID*4);
    cudaMemsetAsync(pc, 0, (size_t)(NN+1)*HID*4);
    bias_perm<<<(G4+255)/256, 256>>>(b1ih, b1hh, bs1);
    bias_perm<<<(G4+255)/256, 256>>>(b2ih, b2hh, bs2);
    detect_map<<<1, 1024>>>((const long long*)mapping_raw);
    convert_map<<<(LL*NN*2 + 255)/256, 256>>>(mapping_raw, map32);

    auto CVTW = [](const float* x, __half* o, int K) {
        long n = (long)G4 * K;
        cvt_perm_w<<<(int)((n + 255) / 256), 256>>>(x, o, K, n);
    };
    auto CVT = [](const float* x, __half* o, long n) {
        long n4 = n / 4;
        cvt_arr4<<<(int)((n4 + 255) / 256), 256>>>((const float4*)x, (__half2*)o, n4);
    };
    CVTW(W1ih, w1ih, COND_D);
    CVTW(W1hh, w1hh, HID);
    CVTW(W2ih, w2ih, IN2);
    CVTW(W2hh, w2hh, HID);
    CVT(condW, condw, (long)MID*HID);
    CVT(cond, cond16, (long)BB*TT*COND_D);

    // ---- phase 1: LSTM1, GEMM + fused cell epilogue (h double-buffered) ----
    dim3 g_big(G4/128, BB/128);   // (16, 128)
    for (int t = 0; t < TT; t++) {
        __half* hr = (t & 1) ? h1b : h1a;
        __half* hw = (t & 1) ? h1a : h1b;
        gemm_mma<<<g_big, 256, SMEM_TOTAL>>>(
            cond16 + (long)t * COND_D, TT*COND_D, COND_D, w1ih,
            hr, HID, (t == 0) ? 0 : HID, w1hh,
            bs1, nullptr, BB, G4, FLAG_CELL1 | (t == 0 ? FLAG_CZERO : 0),
            c1, hw);
    }
    __half* hf = (TT & 1) ? h1b : h1a;

    // ---- phase 2: cond linear + relu, then BN1 stats ----
    dim3 g_cond(MID/128, BB/128);
    gemm_mma<<<g_cond, 256, SMEM_TOTAL>>>(
        hf, HID, HID, condw,
        nullptr, 0, 0, nullptr,
        condb, last, BB, MID, FLAG_RELU,
        nullptr, nullptr);
    bn_stats<<<MID/32, dim3(32,8)>>>(last, BB, MID, mu, rstd);

    // ---- phase 3: concat (fused BN1 apply) + xp2 GEMM ----
    {
        long tot = (long)BB * IN2;
        concat_in2<<<(int)((tot+255)/256), 256>>>(ops, extra, last, mu, rstd, bn1g, bn1b, cat);
    }
    gemm_mma<<<g_big, 256, SMEM_TOTAL>>>(
        cat, IN2, IN2, w2ih,
        nullptr, 0, 0, nullptr,
        bs2, xp2, BB, G4, 0,
        nullptr, nullptr);

    // ---- phase 4: persistent tree LSTM ----
    tree_persistent<<<TREE_CTAS, 256, SMEM_TOTAL>>>(w2hh, xp2, map32, hin, cin, ph, pc);

    // ---- phase 5: fused BN2 -> out ----
    bn2_fused<<<HID/32, dim3(32,8)>>>(ph + HID, bn2g, bn2b, out);
}

// round 15
// speedup vs baseline: 1.4845x; 1.4845x over previous
#include <cuda_runtime.h>
#include <cuda_fp16.h>
#include <cstdint>

// ---------------- problem constants ----------------
#define HID 512
#define MID 256
#define COND_D 256
#define OP_D 32
#define EX_D 32
#define LL 16
#define NN 1024
#define TT 8
#define BB (LL*NN)          // 16384
#define G4 (4*HID)          // 2048
#define IN2 (OP_D+EX_D+MID) // 320
#define TREE_CTAS 128

// ---------------- scratch (device globals; no allocation allowed) ----------------
__device__ __align__(16) __half g_h1[2][BB*HID];
__device__ float g_c1[BB*HID];
__device__ float g_last[BB*MID];
__device__ __align__(16) __half g_cat[BB*IN2];
__device__ float g_xp2[(long)BB*G4];               // gate-interleaved
__device__ float g_ph[(NN+1)*HID];
__device__ float g_pc[(NN+1)*HID];
__device__ __align__(16) __half g_hin[NN*HID];
__device__ float g_cin[NN*HID];
__device__ float g_bs1[G4];                        // gate-interleaved bias
__device__ float g_bs2[G4];
__device__ float g_mu[HID];
__device__ float g_rstd[HID];
__device__ int   g_map32[LL*NN*2];
__device__ int   g_map_is64;
__device__ unsigned int g_bar_gen;
__device__ unsigned int g_bar_cnt;
// fp16 weights (LSTM weights gate-interleaved)
__device__ __align__(16) __half g_w1ih[G4*COND_D];
__device__ __align__(16) __half g_w1hh[G4*HID];
__device__ __align__(16) __half g_condw[MID*HID];
__device__ __align__(16) __half g_w2ih[G4*IN2];
__device__ __align__(16) __half g_w2hh[G4*HID];
__device__ __align__(16) __half g_cond16[(long)BB*TT*COND_D];

// ---------------- low-level helpers ----------------
__device__ __forceinline__ uint32_t smem_u32(const void* p) {
    uint32_t a;
    asm("{ .reg .u64 t; cvta.to.shared.u64 t, %1; cvt.u32.u64 %0, t; }" : "=r"(a) : "l"(p));
    return a;
}
__device__ __forceinline__ void ldmx4(uint32_t* r, uint32_t addr) {
    asm volatile("ldmatrix.sync.aligned.m8n8.x4.shared.b16 {%0,%1,%2,%3}, [%4];"
        : "=r"(r[0]), "=r"(r[1]), "=r"(r[2]), "=r"(r[3]) : "r"(addr));
}
__device__ __forceinline__ void mma16816(float* d, const uint32_t* a, const uint32_t* b) {
    asm volatile("mma.sync.aligned.m16n8k16.row.col.f32.f16.f16.f32 "
        "{%0,%1,%2,%3}, {%4,%5,%6,%7}, {%8,%9}, {%0,%1,%2,%3};"
        : "+f"(d[0]), "+f"(d[1]), "+f"(d[2]), "+f"(d[3])
        : "r"(a[0]), "r"(a[1]), "r"(a[2]), "r"(a[3]), "r"(b[0]), "r"(b[1]));
}
#define CPASYNC16(dst, src) asm volatile("cp.async.cg.shared.global [%0], [%1], 16;" :: "r"(dst), "l"(src))
#define CP_COMMIT() asm volatile("cp.async.commit_group;" ::: "memory")
#define CP_WAIT1()  asm volatile("cp.async.wait_group 1;" ::: "memory")
#define CP_WAIT0()  asm volatile("cp.async.wait_group 0;" ::: "memory")

__device__ __forceinline__ float sigf(float x) { return 1.f / (1.f + expf(-x)); }

// inter-CTA generation barrier (all TREE_CTAS CTAs resident)
__device__ __forceinline__ void grid_sync() {
    __syncthreads();
    if (threadIdx.x == 0) {
        __threadfence();
        unsigned int gen = atomicAdd(&g_bar_gen, 0u);
        if (atomicAdd(&g_bar_cnt, 1u) == TREE_CTAS - 1u) {
            atomicExch(&g_bar_cnt, 0u);
            atomicAdd(&g_bar_gen, 1u);
        } else {
            while (atomicAdd(&g_bar_gen, 0u) == gen) { __nanosleep(64); }
        }
    }
    __syncthreads();
}

#define FLAG_RELU  2
#define FLAG_CELL1 4
#define FLAG_CZERO 16

// ---------------- GEMM tile config ----------------
#define TSZ   16384
#define OFF_A 0
#define OFF_B TSZ
#define BUFSZ  (2*TSZ)          // 32 KB per stage
#define STG_LD 132
#define STG_BYTES (128*STG_LD*4)   // 67584
#define SMEM_TOTAL STG_BYTES

// ---------------- mma.sync fp16 GEMM + optional fused CELL1 epilogue ----------
__global__ __launch_bounds__(256, 2) void gemm_mma(
    const __half* __restrict__ A1, int lda1, int K1, const __half* __restrict__ B1,
    const __half* __restrict__ A2, int lda2, int K2, const __half* __restrict__ B2,
    const float* __restrict__ bias,
    float* __restrict__ C, int M, int N, int flags,
    float* __restrict__ cellc, __half* __restrict__ hout)
{
    extern __shared__ char smem[];
    uint32_t sb = smem_u32(smem);

    int tid = threadIdx.x;
    int wid = tid >> 5, lane = tid & 31;
    int m0 = blockIdx.y * 128, n0 = blockIdx.x * 128;
    int wm = wid & 1, wn = wid >> 1;

    float acc[4][4][4];
    #pragma unroll
    for (int i = 0; i < 4; i++)
        #pragma unroll
        for (int j = 0; j < 4; j++)
            #pragma unroll
            for (int k = 0; k < 4; k++) acc[i][j][k] = 0.f;

    int nc1 = K1 / 64, nc2 = K2 / 64, ncT = nc1 + nc2;
    int r = tid >> 1;
    int half = tid & 1;

    auto issue = [&](int ci, int buf) {
        int ph2 = (ci >= nc1);
        const __half* Ap = ph2 ? A2 : A1;
        const __half* Bp = ph2 ? B2 : B1;
        int lda = ph2 ? lda2 : lda1;
        int ldb = ph2 ? K2 : K1;
        int k0 = (ci - (ph2 ? nc1 : 0)) * 64 + half * 32;
        const __half* pA = Ap + (size_t)(m0 + r) * lda + k0;
        const __half* pB = Bp + (size_t)(n0 + r) * ldb + k0;
        uint32_t base = sb + buf * BUFSZ;
        #pragma unroll
        for (int g = 0; g < 4; g++) {
            uint32_t doff = (uint32_t)(r * 128 + (((half * 4 + g) ^ (r & 7)) * 16));
            CPASYNC16(base + OFF_A + doff, pA + g * 8);
            CPASYNC16(base + OFF_B + doff, pB + g * 8);
        }
    };

    issue(0, 0);
    CP_COMMIT();

    for (int ci = 0; ci < ncT; ci++) {
        if (ci + 1 < ncT) {
            issue(ci + 1, (ci + 1) & 1);
            CP_COMMIT();
            CP_WAIT1();
        } else {
            CP_WAIT0();
        }
        __syncthreads();

        uint32_t base = sb + (ci & 1) * BUFSZ;
        #pragma unroll
        for (int s = 0; s < 4; s++) {
            uint32_t af[4][4];
            #pragma unroll
            for (int mt = 0; mt < 4; mt++) {
                int rr = wm * 64 + mt * 16 + (lane & 15);
                int g = (s * 2 + (lane >> 4)) ^ (rr & 7);
                ldmx4(af[mt], base + OFF_A + (uint32_t)(rr * 128 + g * 16));
            }
            uint32_t bf[4][2];
            #pragma unroll
            for (int ntp = 0; ntp < 2; ntp++) {
                int rr = wn * 32 + ntp * 16 + (lane & 15);
                int g = (s * 2 + (lane >> 4)) ^ (rr & 7);
                uint32_t t[4];
                ldmx4(t, base + OFF_B + (uint32_t)(rr * 128 + g * 16));
                bf[2*ntp][0] = t[0]; bf[2*ntp][1] = t[2];
                bf[2*ntp+1][0] = t[1]; bf[2*ntp+1][1] = t[3];
            }
            #pragma unroll
            for (int mt = 0; mt < 4; mt++)
                #pragma unroll
                for (int nt = 0; nt < 4; nt++)
                    mma16816(acc[mt][nt], af[mt], bf[nt]);
        }
        __syncthreads();
    }

    if (flags & FLAG_CELL1) {
        float* stg = (float*)smem;
        #pragma unroll
        for (int mt = 0; mt < 4; mt++) {
            int rowl = wm * 64 + mt * 16 + (lane >> 2);
            #pragma unroll
            for (int nt = 0; nt < 4; nt++) {
                int coll = wn * 32 + nt * 8 + (lane & 3) * 2;
                float* d = acc[mt][nt];
                *(float2*)&stg[rowl * STG_LD + coll]       = make_float2(d[0], d[1]);
                *(float2*)&stg[(rowl + 8) * STG_LD + coll] = make_float2(d[2], d[3]);
            }
        }
        __syncthreads();
        #pragma unroll
        for (int it = 0; it < 16; it++) {
            int idx = it * 256 + tid;
            int q = idx & 31, rowl = idx >> 5;
            int rowg = m0 + rowl;
            int j = (n0 >> 2) + q;
            float4 v = *(float4*)&stg[rowl * STG_LD + 4 * q];
            float4 b = *(const float4*)(bias + n0 + 4 * q);
            v.x += b.x; v.y += b.y; v.z += b.z; v.w += b.w;
            float ii = sigf(v.x), ff = sigf(v.y), gg = tanhf(v.z), oo = sigf(v.w);
            long ci = (long)rowg * HID + j;
            float cprev = (flags & FLAG_CZERO) ? 0.f : cellc[ci];
            float cn = ff * cprev + ii * gg;
            cellc[ci] = cn;
            hout[ci] = __float2half(oo * tanhf(cn));
        }
    } else {
        #pragma unroll
        for (int mt = 0; mt < 4; mt++) {
            int row0 = m0 + wm * 64 + mt * 16 + (lane >> 2);
            #pragma unroll
            for (int nt = 0; nt < 4; nt++) {
                int col = n0 + wn * 32 + nt * 8 + (lane & 3) * 2;
                float* d = acc[mt][nt];
                float b0 = 0.f, b1 = 0.f;
                if (bias) { b0 = __ldg(bias + col); b1 = __ldg(bias + col + 1); }
                float v0 = d[0] + b0, v1 = d[1] + b1;
                float v2 = d[2] + b0, v3 = d[3] + b1;
                if (flags & FLAG_RELU) {
                    v0 = fmaxf(v0, 0.f); v1 = fmaxf(v1, 0.f);
                    v2 = fmaxf(v2, 0.f); v3 = fmaxf(v3, 0.f);
                }
                float* C0 = C + (size_t)row0 * N + col;
                float* C1 = C + (size_t)(row0 + 8) * N + col;
                C0[0] = v0; C0[1] = v1;
                C1[0] = v2; C1[1] = v3;
            }
        }
    }
}

// ---------------- persistent tree kernel ----------
__global__ __launch_bounds__(256, 1) void tree_persistent(
    const __half* __restrict__ w2hh, const float* __restrict__ xp2,
    const int* __restrict__ map32,
    __half* __restrict__ hin, float* __restrict__ cin,
    float* __restrict__ ph, float* __restrict__ pc)
{
    extern __shared__ char smem[];
    uint32_t sb = smem_u32(smem);
    int tid = threadIdx.x;
    int cb = blockIdx.x;
    int wid = tid >> 5, lane = tid & 31;
    int m0 = (cb >> 4) * 128;
    int n0 = (cb & 15) * 128;
    int wm = wid & 1, wn = wid >> 1;
    int r = tid >> 1;
    int half = tid & 1;

    {
        const float* g0 = xp2 + (long)(LL - 1) * NN * G4;
        #pragma unroll 4
        for (int it = 0; it < 16; it++) {
            int idx = cb * 4096 + it * 256 + tid;
            int b = idx >> 9, j = idx & 511;
            float4 v = *(const float4*)(g0 + (long)b * G4 + 4 * j);
            float ii = sigf(v.x), gg = tanhf(v.z), oo = sigf(v.w);
            float cn = ii * gg;
            pc[(b + 1) * HID + j] = cn;
            ph[(b + 1) * HID + j] = oo * tanhf(cn);
        }
    }
    grid_sync();

    for (int lvl = LL - 2; lvl >= 0; lvl--) {
        const int* mp = map32 + lvl * NN * 2;
        #pragma unroll 4
        for (int it = 0; it < 16; it++) {
            int idx = cb * 4096 + it * 256 + tid;
            int n = idx >> 9, j = idx & 511;
            int a = mp[n * 2], b2 = mp[n * 2 + 1];
            a = min(max(a, 0), NN); b2 = min(max(b2, 0), NN);
            hin[idx] = __float2half(0.5f * (ph[a * HID + j] + ph[b2 * HID + j]));
            cin[idx] = 0.5f * (pc[a * HID + j] + pc[b2 * HID + j]);
        }
        grid_sync();

        float acc[4][4][4];
        #pragma unroll
        for (int i = 0; i < 4; i++)
            #pragma unroll
            for (int j = 0; j < 4; j++)
                #pragma unroll
                for (int k = 0; k < 4; k++) acc[i][j][k] = 0.f;

        auto issue = [&](int ci, int buf) {
            int k0 = ci * 64 + half * 32;
            const __half* pA = hin + (size_t)(m0 + r) * HID + k0;
            const __half* pB = w2hh + (size_t)(n0 + r) * HID + k0;
            uint32_t base = sb + buf * BUFSZ;
            #pragma unroll
            for (int g = 0; g < 4; g++) {
                uint32_t doff = (uint32_t)(r * 128 + (((half * 4 + g) ^ (r & 7)) * 16));
                CPASYNC16(base + OFF_A + doff, pA + g * 8);
                CPASYNC16(base + OFF_B + doff, pB + g * 8);
            }
        };

        issue(0, 0);
        CP_COMMIT();
        for (int ci = 0; ci < 8; ci++) {
            if (ci + 1 < 8) {
                issue(ci + 1, (ci + 1) & 1);
                CP_COMMIT();
                CP_WAIT1();
            } else {
                CP_WAIT0();
            }
            __syncthreads();
            uint32_t base = sb + (ci & 1) * BUFSZ;
            #pragma unroll
            for (int s = 0; s < 4; s++) {
                uint32_t af[4][4];
                #pragma unroll
                for (int mt = 0; mt < 4; mt++) {
                    int rr = wm * 64 + mt * 16 + (lane & 15);
                    int g = (s * 2 + (lane >> 4)) ^ (rr & 7);
                    ldmx4(af[mt], base + OFF_A + (uint32_t)(rr * 128 + g * 16));
                }
                uint32_t bf[4][2];
                #pragma unroll
                for (int ntp = 0; ntp < 2; ntp++) {
                    int rr = wn * 32 + ntp * 16 + (lane & 15);
                    int g = (s * 2 + (lane >> 4)) ^ (rr & 7);
                    uint32_t t[4];
                    ldmx4(t, base + OFF_B + (uint32_t)(rr * 128 + g * 16));
                    bf[2*ntp][0] = t[0]; bf[2*ntp][1] = t[2];
                    bf[2*ntp+1][0] = t[1]; bf[2*ntp+1][1] = t[3];
                }
                #pragma unroll
                for (int mt = 0; mt < 4; mt++)
                    #pragma unroll
                    for (int nt = 0; nt < 4; nt++)
                        mma16816(acc[mt][nt], af[mt], bf[nt]);
            }
            __syncthreads();
        }

        float* stg = (float*)smem;
        #pragma unroll
        for (int mt = 0; mt < 4; mt++) {
            int rowl = wm * 64 + mt * 16 + (lane >> 2);
            #pragma unroll
            for (int nt = 0; nt < 4; nt++) {
                int coll = wn * 32 + nt * 8 + (lane & 3) * 2;
                float* d = acc[mt][nt];
                *(float2*)&stg[rowl * STG_LD + coll]       = make_float2(d[0], d[1]);
                *(float2*)&stg[(rowl + 8) * STG_LD + coll] = make_float2(d[2], d[3]);
            }
        }
        __syncthreads();
        const float* ad = xp2 + (long)lvl * NN * G4;
        #pragma unroll
        for (int it = 0; it < 16; it++) {
            int idx = it * 256 + tid;
            int q = idx & 31, rowl = idx >> 5;
            int rowg = m0 + rowl;
            int j = (n0 >> 2) + q;
            float4 v = *(float4*)&stg[rowl * STG_LD + 4 * q];
            float4 a = *(const float4*)(ad + (size_t)rowg * G4 + n0 + 4 * q);
            v.x += a.x; v.y += a.y; v.z += a.z; v.w += a.w;
            float ii = sigf(v.x), ff = sigf(v.y), gg = tanhf(v.z), oo = sigf(v.w);
            float cn = ff * cin[(long)rowg * HID + j] + ii * gg;
            long po = (long)(rowg + 1) * HID + j;
            pc[po] = cn;
            ph[po] = oo * tanhf(cn);
        }
        grid_sync();
    }
}

// ---------------- conversion kernels (vectorized) ----------------
__global__ void cvt_arr4(const float4* __restrict__ x, __half2* __restrict__ o, long n4) {
    long i = (long)blockIdx.x * blockDim.x + threadIdx.x;
    if (i >= n4) return;
    float4 v = x[i];
    o[i*2]   = __floats2half2_rn(v.x, v.y);
    o[i*2+1] = __floats2half2_rn(v.z, v.w);
}
__global__ void cvt_perm_w(const float* __restrict__ x, __half* __restrict__ o,
                           int K, long n) {
    long idx = (long)blockIdx.x * blockDim.x + threadIdx.x;
    if (idx >= n) return;
    int col = (int)(idx % K);
    long row = idx / K;
    int g = (int)(row >> 9), j = (int)(row & 511);
    o[((long)(4 * j + g)) * K + col] = __float2half(x[idx]);
}
__global__ void bias_perm(const float* __restrict__ bih, const float* __restrict__ bhh,
                          float* __restrict__ o) {
    int i = blockIdx.x * blockDim.x + threadIdx.x;
    if (i >= G4) return;
    int g = i >> 9, j = i & 511;
    o[4 * j + g] = bih[i] + bhh[i];
}

// ---------------- mapping dtype normalization (parallel detect) ----------------
__global__ void detect_map(const long long* __restrict__ raw) {
    __shared__ int bad;
    if (threadIdx.x == 0) bad = 0;
    __syncthreads();
    long long v = raw[threadIdx.x];
    if (v < 0 || v > NN) atomicOr(&bad, 1);
    __syncthreads();
    if (threadIdx.x == 0) g_map_is64 = bad ? 0 : 1;
}
__global__ void convert_map(const void* __restrict__ raw, int* __restrict__ o) {
    int i = blockIdx.x * blockDim.x + threadIdx.x;
    if (i >= LL*NN*2) return;
    if (g_map_is64) o[i] = (int)((const long long*)raw)[i];
    else            o[i] = ((const int*)raw)[i];
}

// ---------------- elementwise kernels ----------------
__global__ void concat_in2(const float* __restrict__ ops, const float* __restrict__ ex,
                           const float* __restrict__ last,
                           const float* __restrict__ mu, const float* __restrict__ rstd,
                           const float* __restrict__ gam, const float* __restrict__ bet,
                           __half* __restrict__ cat) {
    long idx = (long)blockIdx.x * blockDim.x + threadIdx.x;
    if (idx >= (long)BB * IN2) return;
    int r = (int)(idx / IN2), k = (int)(idx % IN2);
    float v;
    if (k < OP_D)            v = ops[(long)r * OP_D + k];
    else if (k < OP_D+EX_D)  v = ex[(long)r * EX_D + (k - OP_D)];
    else {
        int c = k - OP_D - EX_D;
        float x = last[(long)r * MID + c];
        v = gam[c] * (x - mu[c]) * rstd[c] + bet[c];
    }
    cat[idx] = __float2half(v);
}

__global__ void bn_stats(const float* __restrict__ X, int Brows, int C,
                         float* __restrict__ mu, float* __restrict__ rstd) {
    int c = blockIdx.x * 32 + threadIdx.x;
    float s = 0.f, s2 = 0.f;
    for (int r = threadIdx.y; r < Brows; r += 8) {
        float v = X[(long)r * C + c];
        s += v; s2 += v * v;
    }
    __shared__ float sh[8][33], sh2[8][33];
    sh[threadIdx.y][threadIdx.x] = s;
    sh2[threadIdx.y][threadIdx.x] = s2;
    __syncthreads();
    if (threadIdx.y == 0) {
        #pragma unroll
        for (int y = 1; y < 8; y++) { s += sh[y][threadIdx.x]; s2 += sh2[y][threadIdx.x]; }
        float m = s / (float)Brows;
        float var = s2 / (float)Brows - m * m;
        mu[c] = m;
        rstd[c] = rsqrtf(var + 1e-5f);
    }
}

// phase-5: fused BN stats+apply over [NN, HID] -> out
__global__ void bn2_fused(const float* __restrict__ X,
                          const float* __restrict__ gam, const float* __restrict__ bet,
                          float* __restrict__ Y) {
    int c = blockIdx.x * 32 + threadIdx.x;
    float s = 0.f, s2 = 0.f;
    for (int r = threadIdx.y; r < NN; r += 8) {
        float v = X[(long)r * HID + c];
        s += v; s2 += v * v;
    }
    __shared__ float sh[8][33], sh2[8][33], smu[32], srs[32];
    sh[threadIdx.y][threadIdx.x] = s;
    sh2[threadIdx.y][threadIdx.x] = s2;
    __syncthreads();
    if (threadIdx.y == 0) {
        #pragma unroll
        for (int y = 1; y < 8; y++) { s += sh[y][threadIdx.x]; s2 += sh2[y][threadIdx.x]; }
        float m = s / (float)NN;
        float var = s2 / (float)NN - m * m;
        smu[threadIdx.x] = m;
        srs[threadIdx.x] = rsqrtf(var + 1e-5f);
    }
    __syncthreads();
    float m = smu[threadIdx.x], rs = srs[threadIdx.x];
    float gmv = gam[c], btv = bet[c];
    for (int r = threadIdx.y; r < NN; r += 8) {
        float v = X[(long)r * HID + c];
        Y[(long)r * HID + c] = gmv * (v - m) * rs + btv;
    }
}

// ---------------- launch ----------------
extern "C" void kernel_launch(void* const* d_in, const int* in_sizes, int n_in,
                              void* d_out, int out_size) {
    const float* ops   = (const float*)d_in[0];
    const float* extra = (const float*)d_in[1];
    const float* cond  = (const float*)d_in[2];
    const void*  mapping_raw = d_in[4];
    const float* W1ih = (const float*)d_in[5];
    const float* W1hh = (const float*)d_in[6];
    const float* b1ih = (const float*)d_in[7];
    const float* b1hh = (const float*)d_in[8];
    const float* condW = (const float*)d_in[9];
    const float* condb = (const float*)d_in[10];
    const float* bn1g = (const float*)d_in[11];
    const float* bn1b = (const float*)d_in[12];
    const float* W2ih = (const float*)d_in[13];
    const float* W2hh = (const float*)d_in[14];
    const float* b2ih = (const float*)d_in[15];
    const float* b2hh = (const float*)d_in[16];
    const float* bn2g = (const float*)d_in[17];
    const float* bn2b = (const float*)d_in[18];
    float* out = (float*)d_out;

    float *c1,*last,*xp2,*ph,*pc,*cin,*bs1,*bs2,*mu,*rstd;
    __half *h1a,*h1b,*cat,*hin,*w1ih,*w1hh,*condw,*w2ih,*w2hh,*cond16;
    int *map32;
    cudaGetSymbolAddress((void**)&h1a,  g_h1); h1b = h1a + (size_t)BB*HID;
    cudaGetSymbolAddress((void**)&c1,   g_c1);
    cudaGetSymbolAddress((void**)&last, g_last);
    cudaGetSymbolAddress((void**)&cat,  g_cat);
    cudaGetSymbolAddress((void**)&xp2,  g_xp2);
    cudaGetSymbolAddress((void**)&ph,   g_ph);
    cudaGetSymbolAddress((void**)&pc,   g_pc);
    cudaGetSymbolAddress((void**)&hin,  g_hin);
    cudaGetSymbolAddress((void**)&cin,  g_cin);
    cudaGetSymbolAddress((void**)&bs1,  g_bs1);
    cudaGetSymbolAddress((void**)&bs2,  g_bs2);
    cudaGetSymbolAddress((void**)&mu,   g_mu);
    cudaGetSymbolAddress((void**)&rstd, g_rstd);
    cudaGetSymbolAddress((void**)&map32, g_map32);
    cudaGetSymbolAddress((void**)&w1ih, g_w1ih);
    cudaGetSymbolAddress((void**)&w1hh, g_w1hh);
    cudaGetSymbolAddress((void**)&condw, g_condw);
    cudaGetSymbolAddress((void**)&w2ih, g_w2ih);
    cudaGetSymbolAddress((void**)&w2hh, g_w2hh);
    cudaGetSymbolAddress((void**)&cond16, g_cond16);

    cudaFuncSetAttribute(gemm_mma, cudaFuncAttributeMaxDynamicSharedMemorySize, SMEM_TOTAL);
    cudaFuncSetAttribute(tree_persistent, cudaFuncAttributeMaxDynamicSharedMemorySize, SMEM_TOTAL);

    // init (no c1 memset: step 0 uses FLAG_CZERO)
    cudaMemsetAsync(ph, 0, (size_t)(NN+1)*HID*4);
    cudaMemsetAsync(pc, 0, (size_t)(NN+1)*HID*4);
    cudaMemsetAsync(cin, 0, (size_t)NN*HID*4);
    bias_perm<<<(G4+255)/256, 256>>>(b1ih, b1hh, bs1);
    bias_perm<<<(G4+255)/256, 256>>>(b2ih, b2hh, bs2);
    detect_map<<<1, 1024>>>((const long long*)mapping_raw);
    convert_map<<<(LL*NN*2 + 255)/256, 256>>>(mapping_raw, map32);

    auto CVTW = [](const float* x, __half* o, int K) {
        long n = (long)G4 * K;
        cvt_perm_w<<<(int)((n + 255) / 256), 256>>>(x, o, K, n);
    };
    auto CVT = [](const float* x, __half* o, long n) {
        long n4 = n / 4;
        cvt_arr4<<<(int)((n4 + 255) / 256), 256>>>((const float4*)x, (__half2*)o, n4);
    };
    CVTW(W1ih, w1ih, COND_D);
    CVTW(W1hh, w1hh, HID);
    CVTW(W2ih, w2ih, IN2);
    CVTW(W2hh, w2hh, HID);
    CVT(condW, condw, (long)MID*HID);
    CVT(cond, cond16, (long)BB*TT*COND_D);

    // ---- phase 1: LSTM1, GEMM + fused cell epilogue (h double-buffered) ----
    dim3 g_big(G4/128, BB/128);   // (16, 128)
    for (int t = 0; t < TT; t++) {
        __half* hr = (t & 1) ? h1b : h1a;
        __half* hw = (t & 1) ? h1a : h1b;
        gemm_mma<<<g_big, 256, SMEM_TOTAL>>>(
            cond16 + (long)t * COND_D, TT*COND_D, COND_D, w1ih,
            hr, HID, (t == 0) ? 0 : HID, w1hh,
            bs1, nullptr, BB, G4, FLAG_CELL1 | (t == 0 ? FLAG_CZERO : 0),
            c1, hw);
    }
    __half* hf = (TT & 1) ? h1b : h1a;

    // ---- phase 2: cond linear + relu, then BN1 stats ----
    dim3 g_cond(MID/128, BB/128);
    gemm_mma<<<g_cond, 256, SMEM_TOTAL>>>(
        hf, HID, HID, condw,
        nullptr, 0, 0, nullptr,
        condb, last, BB, MID, FLAG_RELU,
        nullptr, nullptr);
    bn_stats<<<MID/32, dim3(32,8)>>>(last, BB, MID, mu, rstd);

    // ---- phase 3: concat (fused BN1 apply) + xp2 GEMM ----
    {
        long tot = (long)BB * IN2;
        concat_in2<<<(int)((tot+255)/256), 256>>>(ops, extra, last, mu, rstd, bn1g, bn1b, cat);
    }
    gemm_mma<<<g_big, 256, SMEM_TOTAL>>>(
        cat, IN2, IN2, w2ih,
        nullptr, 0, 0, nullptr,
        bs2, xp2, BB, G4, 0,
        nullptr, nullptr);

    // ---- phase 4: persistent tree LSTM ----
    tree_persistent<<<TREE_CTAS, 256, SMEM_TOTAL>>>(w2hh, xp2, map32, hin, cin, ph, pc);

    // ---- phase 5: fused BN2 -> out ----
    bn2_fused<<<HID/32, dim3(32,8)>>>(ph + HID, bn2g, bn2b, out);
}

// round 17
// speedup vs baseline: 1.5508x; 1.0447x over previous
#include <cuda_runtime.h>
#include <cuda_fp16.h>
#include <cstdint>

// ---------------- problem constants ----------------
#define HID 512
#define MID 256
#define COND_D 256
#define OP_D 32
#define EX_D 32
#define LL 16
#define NN 1024
#define TT 8
#define BB (LL*NN)          // 16384
#define G4 (4*HID)          // 2048
#define IN2 (OP_D+EX_D+MID) // 320
#define TREE_CTAS 128

// ---------------- scratch (device globals; no allocation allowed) ----------------
__device__ __align__(16) __half g_h1[2][BB*HID];
__device__ float g_c1[BB*HID];
__device__ float g_last[BB*MID];
__device__ __align__(16) __half g_cat[BB*IN2];
__device__ float g_xp2[(long)BB*G4];               // gate-interleaved
__device__ float g_ph[(NN+1)*HID];
__device__ float g_pc[(NN+1)*HID];
__device__ __align__(16) __half g_hin[NN*HID];
__device__ float g_cin[NN*HID];
__device__ float g_bs1[G4];                        // gate-interleaved bias
__device__ float g_bs2[G4];
__device__ float g_mu[HID];
__device__ float g_rstd[HID];
__device__ int   g_map32[LL*NN*2];
__device__ int   g_map_is64;
__device__ unsigned int g_bar_gen;
__device__ unsigned int g_bar_cnt;
// fp16 weights (LSTM weights gate-interleaved)
__device__ __align__(16) __half g_w1ih[G4*COND_D];
__device__ __align__(16) __half g_w1hh[G4*HID];
__device__ __align__(16) __half g_condw[MID*HID];
__device__ __align__(16) __half g_w2ih[G4*IN2];
__device__ __align__(16) __half g_w2hh[G4*HID];
__device__ __align__(16) __half g_cond16[(long)BB*TT*COND_D];

// ---------------- low-level helpers ----------------
__device__ __forceinline__ uint32_t smem_u32(const void* p) {
    uint32_t a;
    asm("{ .reg .u64 t; cvta.to.shared.u64 t, %1; cvt.u32.u64 %0, t; }" : "=r"(a) : "l"(p));
    return a;
}
__device__ __forceinline__ void ldmx4(uint32_t* r, uint32_t addr) {
    asm volatile("ldmatrix.sync.aligned.m8n8.x4.shared.b16 {%0,%1,%2,%3}, [%4];"
        : "=r"(r[0]), "=r"(r[1]), "=r"(r[2]), "=r"(r[3]) : "r"(addr));
}
__device__ __forceinline__ void mma16816(float* d, const uint32_t* a, const uint32_t* b) {
    asm volatile("mma.sync.aligned.m16n8k16.row.col.f32.f16.f16.f32 "
        "{%0,%1,%2,%3}, {%4,%5,%6,%7}, {%8,%9}, {%0,%1,%2,%3};"
        : "+f"(d[0]), "+f"(d[1]), "+f"(d[2]), "+f"(d[3])
        : "r"(a[0]), "r"(a[1]), "r"(a[2]), "r"(a[3]), "r"(b[0]), "r"(b[1]));
}
#define CPASYNC16(dst, src) asm volatile("cp.async.cg.shared.global [%0], [%1], 16;" :: "r"(dst), "l"(src))
#define CP_COMMIT() asm volatile("cp.async.commit_group;" ::: "memory")
#define CP_WAIT1()  asm volatile("cp.async.wait_group 1;" ::: "memory")
#define CP_WAIT0()  asm volatile("cp.async.wait_group 0;" ::: "memory")

__device__ __forceinline__ float sigf(float x) { return 1.f / (1.f + expf(-x)); }

// inter-CTA generation barrier (all TREE_CTAS CTAs resident)
__device__ __forceinline__ void grid_sync() {
    __syncthreads();
    if (threadIdx.x == 0) {
        __threadfence();
        unsigned int gen = atomicAdd(&g_bar_gen, 0u);
        if (atomicAdd(&g_bar_cnt, 1u) == TREE_CTAS - 1u) {
            atomicExch(&g_bar_cnt, 0u);
            atomicAdd(&g_bar_gen, 1u);
        } else {
            while (atomicAdd(&g_bar_gen, 0u) == gen) { __nanosleep(64); }
        }
    }
    __syncthreads();
}

#define FLAG_RELU  2
#define FLAG_CELL1 4
#define FLAG_CZERO 16

// ---------------- GEMM tile config (3-stage cp.async ring) ----------------
#define TSZ   16384
#define OFF_A 0
#define OFF_B TSZ
#define BUFSZ  (2*TSZ)          // 32 KB per stage
#define NSTAGE 3
#define STG_LD 132
#define STG_BYTES (128*STG_LD*4)   // 67584 (aliases stages 0-1)
#define SMEM_TOTAL (NSTAGE*BUFSZ)  // 98304

// ---------------- mma.sync fp16 GEMM + optional fused CELL1 epilogue ----------
__global__ __launch_bounds__(256, 2) void gemm_mma(
    const __half* __restrict__ A1, int lda1, int K1, const __half* __restrict__ B1,
    const __half* __restrict__ A2, int lda2, int K2, const __half* __restrict__ B2,
    const float* __restrict__ bias,
    float* __restrict__ C, int M, int N, int flags,
    float* __restrict__ cellc, __half* __restrict__ hout)
{
    extern __shared__ char smem[];
    uint32_t sb = smem_u32(smem);

    int tid = threadIdx.x;
    int wid = tid >> 5, lane = tid & 31;
    int m0 = blockIdx.y * 128, n0 = blockIdx.x * 128;
    int wm = wid & 1, wn = wid >> 1;

    float acc[4][4][4];
    #pragma unroll
    for (int i = 0; i < 4; i++)
        #pragma unroll
        for (int j = 0; j < 4; j++)
            #pragma unroll
            for (int k = 0; k < 4; k++) acc[i][j][k] = 0.f;

    int nc1 = K1 / 64, nc2 = K2 / 64, ncT = nc1 + nc2;
    int r = tid >> 1;
    int half = tid & 1;

    auto issue = [&](int ci, int buf) {
        int ph2 = (ci >= nc1);
        const __half* Ap = ph2 ? A2 : A1;
        const __half* Bp = ph2 ? B2 : B1;
        int lda = ph2 ? lda2 : lda1;
        int ldb = ph2 ? K2 : K1;
        int k0 = (ci - (ph2 ? nc1 : 0)) * 64 + half * 32;
        const __half* pA = Ap + (size_t)(m0 + r) * lda + k0;
        const __half* pB = Bp + (size_t)(n0 + r) * ldb + k0;
        uint32_t base = sb + buf * BUFSZ;
        #pragma unroll
        for (int g = 0; g < 4; g++) {
            uint32_t doff = (uint32_t)(r * 128 + (((half * 4 + g) ^ (r & 7)) * 16));
            CPASYNC16(base + OFF_A + doff, pA + g * 8);
            CPASYNC16(base + OFF_B + doff, pB + g * 8);
        }
    };

    issue(0, 0);
    CP_COMMIT();
    if (ncT > 1) { issue(1, 1); CP_COMMIT(); }

    for (int ci = 0; ci < ncT; ci++) {
        if (ci + 1 < ncT) CP_WAIT1(); else CP_WAIT0();
        __syncthreads();

        uint32_t base = sb + (uint32_t)(ci % NSTAGE) * BUFSZ;
        #pragma unroll
        for (int s = 0; s < 4; s++) {
            uint32_t af[4][4];
            #pragma unroll
            for (int mt = 0; mt < 4; mt++) {
                int rr = wm * 64 + mt * 16 + (lane & 15);
                int g = (s * 2 + (lane >> 4)) ^ (rr & 7);
                ldmx4(af[mt], base + OFF_A + (uint32_t)(rr * 128 + g * 16));
            }
            uint32_t bf[4][2];
            #pragma unroll
            for (int ntp = 0; ntp < 2; ntp++) {
                int rr = wn * 32 + ntp * 16 + (lane & 15);
                int g = (s * 2 + (lane >> 4)) ^ (rr & 7);
                uint32_t t[4];
                ldmx4(t, base + OFF_B + (uint32_t)(rr * 128 + g * 16));
                bf[2*ntp][0] = t[0]; bf[2*ntp][1] = t[2];
                bf[2*ntp+1][0] = t[1]; bf[2*ntp+1][1] = t[3];
            }
            #pragma unroll
            for (int mt = 0; mt < 4; mt++)
                #pragma unroll
                for (int nt = 0; nt < 4; nt++)
                    mma16816(acc[mt][nt], af[mt], bf[nt]);
        }

        if (ci + 2 < ncT) { issue(ci + 2, (ci + 2) % NSTAGE); CP_COMMIT(); }
    }

    if (flags & FLAG_CELL1) {
        __syncthreads();   // buffers alias staging area
        float* stg = (float*)smem;
        #pragma unroll
        for (int mt = 0; mt < 4; mt++) {
            int rowl = wm * 64 + mt * 16 + (lane >> 2);
            #pragma unroll
            for (int nt = 0; nt < 4; nt++) {
                int coll = wn * 32 + nt * 8 + (lane & 3) * 2;
                float* d = acc[mt][nt];
                *(float2*)&stg[rowl * STG_LD + coll]       = make_float2(d[0], d[1]);
                *(float2*)&stg[(rowl + 8) * STG_LD + coll] = make_float2(d[2], d[3]);
            }
        }
        __syncthreads();
        #pragma unroll
        for (int it = 0; it < 16; it++) {
            int idx = it * 256 + tid;
            int q = idx & 31, rowl = idx >> 5;
            int rowg = m0 + rowl;
            int j = (n0 >> 2) + q;
            float4 v = *(float4*)&stg[rowl * STG_LD + 4 * q];
            float4 b = *(const float4*)(bias + n0 + 4 * q);
            v.x += b.x; v.y += b.y; v.z += b.z; v.w += b.w;
            float ii = sigf(v.x), ff = sigf(v.y), gg = tanhf(v.z), oo = sigf(v.w);
            long ci = (long)rowg * HID + j;
            float cprev = (flags & FLAG_CZERO) ? 0.f : cellc[ci];
            float cn = ff * cprev + ii * gg;
            cellc[ci] = cn;
            hout[ci] = __float2half(oo * tanhf(cn));
        }
    } else {
        #pragma unroll
        for (int mt = 0; mt < 4; mt++) {
            int row0 = m0 + wm * 64 + mt * 16 + (lane >> 2);
            #pragma unroll
            for (int nt = 0; nt < 4; nt++) {
                int col = n0 + wn * 32 + nt * 8 + (lane & 3) * 2;
                float* d = acc[mt][nt];
                float b0 = 0.f, b1 = 0.f;
                if (bias) { b0 = __ldg(bias + col); b1 = __ldg(bias + col + 1); }
                float v0 = d[0] + b0, v1 = d[1] + b1;
                float v2 = d[2] + b0, v3 = d[3] + b1;
                if (flags & FLAG_RELU) {
                    v0 = fmaxf(v0, 0.f); v1 = fmaxf(v1, 0.f);
                    v2 = fmaxf(v2, 0.f); v3 = fmaxf(v3, 0.f);
                }
                float* C0 = C + (size_t)row0 * N + col;
                float* C1 = C + (size_t)(row0 + 8) * N + col;
                C0[0] = v0; C0[1] = v1;
                C1[0] = v2; C1[1] = v3;
            }
        }
    }
}

// ---------------- persistent tree kernel (3-stage ring in GEMM) ----------
__global__ __launch_bounds__(256, 1) void tree_persistent(
    const __half* __restrict__ w2hh, const float* __restrict__ xp2,
    const int* __restrict__ map32,
    __half* __restrict__ hin, float* __restrict__ cin,
    float* __restrict__ ph, float* __restrict__ pc)
{
    extern __shared__ char smem[];
    uint32_t sb = smem_u32(smem);
    int tid = threadIdx.x;
    int cb = blockIdx.x;
    int wid = tid >> 5, lane = tid & 31;
    int m0 = (cb >> 4) * 128;
    int n0 = (cb & 15) * 128;
    int wm = wid & 1, wn = wid >> 1;
    int r = tid >> 1;
    int half = tid & 1;

    {
        const float* g0 = xp2 + (long)(LL - 1) * NN * G4;
        #pragma unroll 4
        for (int it = 0; it < 16; it++) {
            int idx = cb * 4096 + it * 256 + tid;
            int b = idx >> 9, j = idx & 511;
            float4 v = *(const float4*)(g0 + (long)b * G4 + 4 * j);
            float ii = sigf(v.x), gg = tanhf(v.z), oo = sigf(v.w);
            float cn = ii * gg;
            pc[(b + 1) * HID + j] = cn;
            ph[(b + 1) * HID + j] = oo * tanhf(cn);
        }
    }
    grid_sync();

    for (int lvl = LL - 2; lvl >= 0; lvl--) {
        const int* mp = map32 + lvl * NN * 2;
        #pragma unroll 4
        for (int it = 0; it < 16; it++) {
            int idx = cb * 4096 + it * 256 + tid;
            int n = idx >> 9, j = idx & 511;
            int a = mp[n * 2], b2 = mp[n * 2 + 1];
            a = min(max(a, 0), NN); b2 = min(max(b2, 0), NN);
            hin[idx] = __float2half(0.5f * (ph[a * HID + j] + ph[b2 * HID + j]));
            cin[idx] = 0.5f * (pc[a * HID + j] + pc[b2 * HID + j]);
        }
        grid_sync();

        float acc[4][4][4];
        #pragma unroll
        for (int i = 0; i < 4; i++)
            #pragma unroll
            for (int j = 0; j < 4; j++)
                #pragma unroll
                for (int k = 0; k < 4; k++) acc[i][j][k] = 0.f;

        auto issue = [&](int ci, int buf) {
            int k0 = ci * 64 + half * 32;
            const __half* pA = hin + (size_t)(m0 + r) * HID + k0;
            const __half* pB = w2hh + (size_t)(n0 + r) * HID + k0;
            uint32_t base = sb + buf * BUFSZ;
            #pragma unroll
            for (int g = 0; g < 4; g++) {
                uint32_t doff = (uint32_t)(r * 128 + (((half * 4 + g) ^ (r & 7)) * 16));
                CPASYNC16(base + OFF_A + doff, pA + g * 8);
                CPASYNC16(base + OFF_B + doff, pB + g * 8);
            }
        };

        issue(0, 0);
        CP_COMMIT();
        issue(1, 1);
        CP_COMMIT();
        for (int ci = 0; ci < 8; ci++) {
            if (ci + 1 < 8) CP_WAIT1(); else CP_WAIT0();
            __syncthreads();
            uint32_t base = sb + (uint32_t)(ci % NSTAGE) * BUFSZ;
            #pragma unroll
            for (int s = 0; s < 4; s++) {
                uint32_t af[4][4];
                #pragma unroll
                for (int mt = 0; mt < 4; mt++) {
                    int rr = wm * 64 + mt * 16 + (lane & 15);
                    int g = (s * 2 + (lane >> 4)) ^ (rr & 7);
                    ldmx4(af[mt], base + OFF_A + (uint32_t)(rr * 128 + g * 16));
                }
                uint32_t bf[4][2];
                #pragma unroll
                for (int ntp = 0; ntp < 2; ntp++) {
                    int rr = wn * 32 + ntp * 16 + (lane & 15);
                    int g = (s * 2 + (lane >> 4)) ^ (rr & 7);
                    uint32_t t[4];
                    ldmx4(t, base + OFF_B + (uint32_t)(rr * 128 + g * 16));
                    bf[2*ntp][0] = t[0]; bf[2*ntp][1] = t[2];
                    bf[2*ntp+1][0] = t[1]; bf[2*ntp+1][1] = t[3];
                }
                #pragma unroll
                for (int mt = 0; mt < 4; mt++)
                    #pragma unroll
                    for (int nt = 0; nt < 4; nt++)
                        mma16816(acc[mt][nt], af[mt], bf[nt]);
            }
            if (ci + 2 < 8) { issue(ci + 2, (ci + 2) % NSTAGE); CP_COMMIT(); }
        }

        __syncthreads();   // buffers alias staging area
        float* stg = (float*)smem;
        #pragma unroll
        for (int mt = 0; mt < 4; mt++) {
            int rowl = wm * 64 + mt * 16 + (lane >> 2);
            #pragma unroll
            for (int nt = 0; nt < 4; nt++) {
                int coll = wn * 32 + nt * 8 + (lane & 3) * 2;
                float* d = acc[mt][nt];
                *(float2*)&stg[rowl * STG_LD + coll]       = make_float2(d[0], d[1]);
                *(float2*)&stg[(rowl + 8) * STG_LD + coll] = make_float2(d[2], d[3]);
            }
        }
        __syncthreads();
        const float* ad = xp2 + (long)lvl * NN * G4;
        #pragma unroll
        for (int it = 0; it < 16; it++) {
            int idx = it * 256 + tid;
            int q = idx & 31, rowl = idx >> 5;
            int rowg = m0 + rowl;
            int j = (n0 >> 2) + q;
            float4 v = *(float4*)&stg[rowl * STG_LD + 4 * q];
            float4 a = *(const float4*)(ad + (size_t)rowg * G4 + n0 + 4 * q);
            v.x += a.x; v.y += a.y; v.z += a.z; v.w += a.w;
            float ii = sigf(v.x), ff = sigf(v.y), gg = tanhf(v.z), oo = sigf(v.w);
            float cn = ff * cin[(long)rowg * HID + j] + ii * gg;
            long po = (long)(rowg + 1) * HID + j;
            pc[po] = cn;
            ph[po] = oo * tanhf(cn);
        }
        grid_sync();
    }
}

// ---------------- conversion kernels (vectorized) ----------------
__global__ void cvt_arr4(const float4* __restrict__ x, __half2* __restrict__ o, long n4) {
    long i = (long)blockIdx.x * blockDim.x + threadIdx.x;
    if (i >= n4) return;
    float4 v = x[i];
    o[i*2]   = __floats2half2_rn(v.x, v.y);
    o[i*2+1] = __floats2half2_rn(v.z, v.w);
}
__global__ void cvt_perm_w(const float* __restrict__ x, __half* __restrict__ o,
                           int K, long n) {
    long idx = (long)blockIdx.x * blockDim.x + threadIdx.x;
    if (idx >= n) return;
    int col = (int)(idx % K);
    long row = idx / K;
    int g = (int)(row >> 9), j = (int)(row & 511);
    o[((long)(4 * j + g)) * K + col] = __float2half(x[idx]);
}
__global__ void bias_perm(const float* __restrict__ bih, const float* __restrict__ bhh,
                          float* __restrict__ o) {
    int i = blockIdx.x * blockDim.x + threadIdx.x;
    if (i >= G4) return;
    int g = i >> 9, j = i & 511;
    o[4 * j + g] = bih[i] + bhh[i];
}

// ---------------- mapping dtype normalization (parallel detect) ----------------
__global__ void detect_map(const long long* __restrict__ raw) {
    __shared__ int bad;
    if (threadIdx.x == 0) bad = 0;
    __syncthreads();
    long long v = raw[threadIdx.x];
    if (v < 0 || v > NN) atomicOr(&bad, 1);
    __syncthreads();
    if (threadIdx.x == 0) g_map_is64 = bad ? 0 : 1;
}
__global__ void convert_map(const void* __restrict__ raw, int* __restrict__ o) {
    int i = blockIdx.x * blockDim.x + threadIdx.x;
    if (i >= LL*NN*2) return;
    if (g_map_is64) o[i] = (int)((const long long*)raw)[i];
    else            o[i] = ((const int*)raw)[i];
}

// ---------------- elementwise kernels ----------------
__global__ void concat_in2(const float* __restrict__ ops, const float* __restrict__ ex,
                           const float* __restrict__ last,
                           const float* __restrict__ mu, const float* __restrict__ rstd,
                           const float* __restrict__ gam, const float* __restrict__ bet,
                           __half* __restrict__ cat) {
    long idx = (long)blockIdx.x * blockDim.x + threadIdx.x;
    if (idx >= (long)BB * IN2) return;
    int r = (int)(idx / IN2), k = (int)(idx % IN2);
    float v;
    if (k < OP_D)            v = ops[(long)r * OP_D + k];
    else if (k < OP_D+EX_D)  v = ex[(long)r * EX_D + (k - OP_D)];
    else {
        int c = k - OP_D - EX_D;
        float x = last[(long)r * MID + c];
        v = gam[c] * (x - mu[c]) * rstd[c] + bet[c];
    }
    cat[idx] = __float2half(v);
}

__global__ void bn_stats(const float* __restrict__ X, int Brows, int C,
                         float* __restrict__ mu, float* __restrict__ rstd) {
    int c = blockIdx.x * 32 + threadIdx.x;
    float s = 0.f, s2 = 0.f;
    for (int r = threadIdx.y; r < Brows; r += 8) {
        float v = X[(long)r * C + c];
        s += v; s2 += v * v;
    }
    __shared__ float sh[8][33], sh2[8][33];
    sh[threadIdx.y][threadIdx.x] = s;
    sh2[threadIdx.y][threadIdx.x] = s2;
    __syncthreads();
    if (threadIdx.y == 0) {
        #pragma unroll
        for (int y = 1; y < 8; y++) { s += sh[y][threadIdx.x]; s2 += sh2[y][threadIdx.x]; }
        float m = s / (float)Brows;
        float var = s2 / (float)Brows - m * m;
        mu[c] = m;
        rstd[c] = rsqrtf(var + 1e-5f);
    }
}

// phase-5: fused BN stats+apply over [NN, HID] -> out
__global__ void bn2_fused(const float* __restrict__ X,
                          const float* __restrict__ gam, const float* __restrict__ bet,
                          float* __restrict__ Y) {
    int c = blockIdx.x * 32 + threadIdx.x;
    float s = 0.f, s2 = 0.f;
    for (int r = threadIdx.y; r < NN; r += 8) {
        float v = X[(long)r * HID + c];
        s += v; s2 += v * v;
    }
    __shared__ float sh[8][33], sh2[8][33], smu[32], srs[32];
    sh[threadIdx.y][threadIdx.x] = s;
    sh2[threadIdx.y][threadIdx.x] = s2;
    __syncthreads();
    if (threadIdx.y == 0) {
        #pragma unroll
        for (int y = 1; y < 8; y++) { s += sh[y][threadIdx.x]; s2 += sh2[y][threadIdx.x]; }
        float m = s / (float)NN;
        float var = s2 / (float)NN - m * m;
        smu[threadIdx.x] = m;
        srs[threadIdx.x] = rsqrtf(var + 1e-5f);
    }
    __syncthreads();
    float m = smu[threadIdx.x], rs = srs[threadIdx.x];
    float gmv = gam[c], btv = bet[c];
    for (int r = threadIdx.y; r < NN; r += 8) {
        float v = X[(long)r * HID + c];
        Y[(long)r * HID + c] = gmv * (v - m) * rs + btv;
    }
}

// ---------------- launch ----------------
extern "C" void kernel_launch(void* const* d_in, const int* in_sizes, int n_in,
                              void* d_out, int out_size) {
    const float* ops   = (const float*)d_in[0];
    const float* extra = (const float*)d_in[1];
    const float* cond  = (const float*)d_in[2];
    const void*  mapping_raw = d_in[4];
    const float* W1ih = (const float*)d_in[5];
    const float* W1hh = (const float*)d_in[6];
    const float* b1ih = (const float*)d_in[7];
    const float* b1hh = (const float*)d_in[8];
    const float* condW = (const float*)d_in[9];
    const float* condb = (const float*)d_in[10];
    const float* bn1g = (const float*)d_in[11];
    const float* bn1b = (const float*)d_in[12];
    const float* W2ih = (const float*)d_in[13];
    const float* W2hh = (const float*)d_in[14];
    const float* b2ih = (const float*)d_in[15];
    const float* b2hh = (const float*)d_in[16];
    const float* bn2g = (const float*)d_in[17];
    const float* bn2b = (const float*)d_in[18];
    float* out = (float*)d_out;

    float *c1,*last,*xp2,*ph,*pc,*cin,*bs1,*bs2,*mu,*rstd;
    __half *h1a,*h1b,*cat,*hin,*w1ih,*w1hh,*condw,*w2ih,*w2hh,*cond16;
    int *map32;
    cudaGetSymbolAddress((void**)&h1a,  g_h1); h1b = h1a + (size_t)BB*HID;
    cudaGetSymbolAddress((void**)&c1,   g_c1);
    cudaGetSymbolAddress((void**)&last, g_last);
    cudaGetSymbolAddress((void**)&cat,  g_cat);
    cudaGetSymbolAddress((void**)&xp2,  g_xp2);
    cudaGetSymbolAddress((void**)&ph,   g_ph);
    cudaGetSymbolAddress((void**)&pc,   g_pc);
    cudaGetSymbolAddress((void**)&hin,  g_hin);
    cudaGetSymbolAddress((void**)&cin,  g_cin);
    cudaGetSymbolAddress((void**)&bs1,  g_bs1);
    cudaGetSymbolAddress((void**)&bs2,  g_bs2);
    cudaGetSymbolAddress((void**)&mu,   g_mu);
    cudaGetSymbolAddress((void**)&rstd, g_rstd);
    cudaGetSymbolAddress((void**)&map32, g_map32);
    cudaGetSymbolAddress((void**)&w1ih, g_w1ih);
    cudaGetSymbolAddress((void**)&w1hh, g_w1hh);
    cudaGetSymbolAddress((void**)&condw, g_condw);
    cudaGetSymbolAddress((void**)&w2ih, g_w2ih);
    cudaGetSymbolAddress((void**)&w2hh, g_w2hh);
    cudaGetSymbolAddress((void**)&cond16, g_cond16);

    cudaFuncSetAttribute(gemm_mma, cudaFuncAttributeMaxDynamicSharedMemorySize, SMEM_TOTAL);
    cudaFuncSetAttribute(tree_persistent, cudaFuncAttributeMaxDynamicSharedMemorySize, SMEM_TOTAL);

    // init (no c1 memset: step 0 uses FLAG_CZERO)
    cudaMemsetAsync(ph, 0, (size_t)(NN+1)*HID*4);
    cudaMemsetAsync(pc, 0, (size_t)(NN+1)*HID*4);
    cudaMemsetAsync(cin, 0, (size_t)NN*HID*4);
    bias_perm<<<(G4+255)/256, 256>>>(b1ih, b1hh, bs1);
    bias_perm<<<(G4+255)/256, 256>>>(b2ih, b2hh, bs2);
    detect_map<<<1, 1024>>>((const long long*)mapping_raw);
    convert_map<<<(LL*NN*2 + 255)/256, 256>>>(mapping_raw, map32);

    auto CVTW = [](const float* x, __half* o, int K) {
        long n = (long)G4 * K;
        cvt_perm_w<<<(int)((n + 255) / 256), 256>>>(x, o, K, n);
    };
    auto CVT = [](const float* x, __half* o, long n) {
        long n4 = n / 4;
        cvt_arr4<<<(int)((n4 + 255) / 256), 256>>>((const float4*)x, (__half2*)o, n4);
    };
    CVTW(W1ih, w1ih, COND_D);
    CVTW(W1hh, w1hh, HID);
    CVTW(W2ih, w2ih, IN2);
    CVTW(W2hh, w2hh, HID);
    CVT(condW, condw, (long)MID*HID);
    CVT(cond, cond16, (long)BB*TT*COND_D);

    // ---- phase 1: LSTM1, GEMM + fused cell epilogue (h double-buffered) ----
    dim3 g_big(G4/128, BB/128);   // (16, 128)
    for (int t = 0; t < TT; t++) {
        __half* hr = (t & 1) ? h1b : h1a;
        __half* hw = (t & 1) ? h1a : h1b;
        gemm_mma<<<g_big, 256, SMEM_TOTAL>>>(
            cond16 + (long)t * COND_D, TT*COND_D, COND_D, w1ih,
            hr, HID, (t == 0) ? 0 : HID, w1hh,
            bs1, nullptr, BB, G4, FLAG_CELL1 | (t == 0 ? FLAG_CZERO : 0),
            c1, hw);
    }
    __half* hf = (TT & 1) ? h1b : h1a;

    // ---- phase 2: cond linear + relu, then BN1 stats ----
    dim3 g_cond(MID/128, BB/128);
    gemm_mma<<<g_cond, 256, SMEM_TOTAL>>>(
        hf, HID, HID, condw,
        nullptr, 0, 0, nullptr,
        condb, last, BB, MID, FLAG_RELU,
        nullptr, nullptr);
    bn_stats<<<MID/32, dim3(32,8)>>>(last, BB, MID, mu, rstd);

    // ---- phase 3: concat (fused BN1 apply) + xp2 GEMM ----
    {
        long tot = (long)BB * IN2;
        concat_in2<<<(int)((tot+255)/256), 256>>>(ops, extra, last, mu, rstd, bn1g, bn1b, cat);
    }
    gemm_mma<<<g_big, 256, SMEM_TOTAL>>>(
        cat, IN2, IN2, w2ih,
        nullptr, 0, 0, nullptr,
        bs2, xp2, BB, G4, 0,
        nullptr, nullptr);

    // ---- phase 4: persistent tree LSTM ----
    tree_persistent<<<TREE_CTAS, 256, SMEM_TOTAL>>>(w2hh, xp2, map32, hin, cin, ph, pc);

    // ---- phase 5: fused BN2 -> out ----
    bn2_fused<<<HID/32, dim3(32,8)>>>(ph + HID, bn2g, bn2b, out);
}